// round 13
// baseline (speedup 1.0000x reference)
#include <cuda_runtime.h>
#include <cuda_fp16.h>
#include <math.h>
#include <stdint.h>

// Problem shape (fixed)
#define B   2
#define T   2048
#define KD  256
#define H   8
#define BH  (B*H)        // 16
#define NPROJ (KD*H)     // 2048
#define ROWS (B*T)       // 4096

#define LOG2E 1.4426950408889634f
#define KSPLIT 4

// ---------------------------------------------------------------------------
// Scratch (device globals — allocation-free per harness rules)
// ---------------------------------------------------------------------------
__device__ __half g_Xh [ROWS * KD];            // x in fp16
__device__ __half g_Qh [BH * T * KD];          // [bh][t][kd] * 0.25*log2e
__device__ __half g_Kh [BH * T * KD];          // [bh][t][kd] * 0.25
__device__ __half g_Vth[BH * KD * T];          // [bh][kd][t]
__device__ __half g_Oh [ROWS * NPROJ];         // [b*t][h*kd]
__device__ __half g_Wth [3 * NPROJ * KD];      // Wq^T,Wk^T,Wv^T fp16 [n][k]
__device__ __half g_Wuth[KD * NPROJ];          // Wu^T fp16 [256][2048]

// ---------------------------------------------------------------------------
// Common PTX helpers
// ---------------------------------------------------------------------------
__device__ __forceinline__ uint32_t smem_u32(const void* p) {
    uint32_t a;
    asm("{ .reg .u64 t; cvta.to.shared.u64 t, %1; cvt.u32.u64 %0, t; }"
        : "=r"(a) : "l"(p));
    return a;
}
__device__ __forceinline__ uint32_t packh2(float x, float y) {
    __half2 h = __floats2half2_rn(x, y);
    return *(uint32_t*)&h;
}
#define LDSM_X4(r0, r1, r2, r3, addr) \
    asm volatile("ldmatrix.sync.aligned.m8n8.x4.shared.b16 {%0,%1,%2,%3}, [%4];" \
                 : "=r"(r0), "=r"(r1), "=r"(r2), "=r"(r3) : "r"(addr))
#define CP_ASYNC16(dst, src) \
    asm volatile("cp.async.cg.shared.global [%0], [%1], 16;" :: "r"(dst), "l"(src))
#define CP_COMMIT() asm volatile("cp.async.commit_group;" ::: "memory")
#define CP_WAIT(n)  asm volatile("cp.async.wait_group %0;" :: "n"(n) : "memory")

__device__ __forceinline__ void mma16(float c[4], const uint32_t a[4],
                                      const uint32_t b[2]) {
    asm volatile(
        "mma.sync.aligned.m16n8k16.row.col.f32.f16.f16.f32 "
        "{%0,%1,%2,%3}, {%4,%5,%6,%7}, {%8,%9}, {%0,%1,%2,%3};"
        : "+f"(c[0]), "+f"(c[1]), "+f"(c[2]), "+f"(c[3])
        : "r"(a[0]), "r"(a[1]), "r"(a[2]), "r"(a[3]), "r"(b[0]), "r"(b[1]));
}

// ===========================================================================
// GEMM engine (proj + final: both 128x128 tiles; final uses split-K=4)
// ===========================================================================
#define BK    32
#define LDSW  40

#define MODE_PROJ   0
#define MODE_FINAL  3

template <int MODE>
__global__ void __launch_bounds__(256, 2)
gemm_mma(const float* __restrict__ pBias, float* __restrict__ pC) {
    constexpr int TM = 128;
    constexpr int TN = 128;
    constexpr int MI = TM / 32;
    constexpr int ABUF = TM * LDSW;
    constexpr int BBUF = TN * LDSW;

    extern __shared__ __half smem[];
    const uint32_t sb0 = smem_u32(smem);
    const uint32_t aB[2] = { sb0, sb0 + ABUF * 2 };
    const uint32_t bB[2] = { sb0 + 2 * ABUF * 2, sb0 + 2 * ABUF * 2 + BBUF * 2 };

    const int tid  = threadIdx.x;
    const int lane = tid & 31, wid = tid >> 5;
    const int g    = lane >> 2, tig = lane & 3;
    const int wm   = (wid & 1) * (TM / 2);
    const int wn   = (wid >> 1) * 32;
    const int m0   = blockIdx.y * TM, n0 = blockIdx.x * TN;
    const int z    = blockIdx.z;

    const __half *Ah, *Bh;
    int lda, ldb, nch, kbase;
    if (MODE == MODE_PROJ) {
        Ah = g_Xh; lda = KD;
        Bh = g_Wth + (size_t)z * NPROJ * KD; ldb = KD;
        nch = KD / BK; kbase = 0;
    } else {
        Ah = g_Oh;   lda = NPROJ;
        Bh = g_Wuth; ldb = NPROJ;
        nch = NPROJ / BK / KSPLIT;               // 16 chunks per split
        kbase = z * (NPROJ / KSPLIT);            // 512 * z
    }

    auto issue_chunk = [&](int c, int st) {
        const int k0 = kbase + c * BK;
        #pragma unroll
        for (int u = tid; u < TM * 4; u += 256) {
            const int r = u >> 2, cc = (u & 3) * 8;
            CP_ASYNC16(aB[st] + (uint32_t)((r * LDSW + cc) * 2),
                       &Ah[(size_t)(m0 + r) * lda + k0 + cc]);
        }
        #pragma unroll
        for (int u = tid; u < TN * 4; u += 256) {
            const int r = u >> 2, cc = (u & 3) * 8;
            CP_ASYNC16(bB[st] + (uint32_t)((r * LDSW + cc) * 2),
                       &Bh[(size_t)(n0 + r) * ldb + k0 + cc]);
        }
    };

    float acc[MI][4][4];
    #pragma unroll
    for (int mi = 0; mi < MI; mi++)
        #pragma unroll
        for (int ni = 0; ni < 4; ni++)
            #pragma unroll
            for (int r = 0; r < 4; r++) acc[mi][ni][r] = 0.f;

    const int lm_row = lane & 15, lm_k8 = (lane >> 4) * 8;

    issue_chunk(0, 0); CP_COMMIT();
    issue_chunk(1, 1); CP_COMMIT();

    for (int c = 0; c < nch; c++) {
        const int st = c & 1;
        if (c + 1 < nch) CP_WAIT(1); else CP_WAIT(0);
        __syncthreads();
        #pragma unroll
        for (int ks = 0; ks < 2; ks++) {
            const int k = ks * 16;
            uint32_t af[MI][4], bf[4][2];
            #pragma unroll
            for (int mi = 0; mi < MI; mi++) {
                uint32_t ad = aB[st] +
                    (uint32_t)(((wm + mi * 16 + lm_row) * LDSW + k + lm_k8) * 2);
                LDSM_X4(af[mi][0], af[mi][1], af[mi][2], af[mi][3], ad);
            }
            #pragma unroll
            for (int nj = 0; nj < 2; nj++) {
                uint32_t bd = bB[st] +
                    (uint32_t)(((wn + nj * 16 + lm_row) * LDSW + k + lm_k8) * 2);
                LDSM_X4(bf[2 * nj][0], bf[2 * nj + 1][0],
                        bf[2 * nj][1], bf[2 * nj + 1][1], bd);
            }
            #pragma unroll
            for (int mi = 0; mi < MI; mi++)
                #pragma unroll
                for (int ni = 0; ni < 4; ni++)
                    mma16(acc[mi][ni], af[mi], bf[ni]);
        }
        __syncthreads();
        if (c + 2 < nch) { issue_chunk(c + 2, st); CP_COMMIT(); }
    }

    // ------------------- epilogue -------------------------------
    if (MODE == MODE_PROJ && z == 2) {
        // V: stage transposed tile in smem, then coalesced column writes.
        __half* epi = smem;
        #pragma unroll
        for (int mi = 0; mi < MI; mi++) {
            const int rl0 = wm + mi * 16 + g;
            #pragma unroll
            for (int ni = 0; ni < 4; ni++) {
                const int cl = wn + ni * 8 + tig * 2;
                const float* v = acc[mi][ni];
                epi[(cl)     * 136 + rl0]     = __float2half_rn(v[0]);
                epi[(cl + 1) * 136 + rl0]     = __float2half_rn(v[1]);
                epi[(cl)     * 136 + rl0 + 8] = __float2half_rn(v[2]);
                epi[(cl + 1) * 136 + rl0 + 8] = __float2half_rn(v[3]);
            }
        }
        __syncthreads();
        const int head = n0 >> 8;
        const int colh0 = n0 & 255;
        const int b_ = m0 >> 11, t0 = m0 & 2047;
        const int col = tid >> 1, sub = tid & 1;
        __half* dst = g_Vth + (((size_t)(b_ * H + head)) * KD + colh0 + col) * T + t0;
        #pragma unroll
        for (int j = 0; j < 8; j++) {
            const int row = sub * 8 + j * 16;
            *(uint4*)&dst[row] = *(const uint4*)&epi[col * 136 + row];
        }
        return;
    }

    #pragma unroll
    for (int mi = 0; mi < MI; mi++) {
        const int r0 = m0 + wm + mi * 16 + g;
        const int r1 = r0 + 8;
        #pragma unroll
        for (int ni = 0; ni < 4; ni++) {
            const int cc = n0 + wn + ni * 8 + tig * 2;
            const float* v = acc[mi][ni];
            if (MODE == MODE_PROJ) {
                const int head = n0 >> 8;
                const int colh = (n0 & 255) + wn + ni * 8 + tig * 2;
                const int b0_ = r0 >> 11, t0_ = r0 & 2047;
                const int b1_ = r1 >> 11, t1_ = r1 & 2047;
                const float scale = (z == 0) ? 0.25f * LOG2E : 0.25f;
                __half* Cb = (z == 0) ? g_Qh : g_Kh;
                *(uint32_t*)&Cb[(((size_t)(b0_ * H + head)) * T + t0_) * KD + colh] =
                    packh2(v[0] * scale, v[1] * scale);
                *(uint32_t*)&Cb[(((size_t)(b1_ * H + head)) * T + t1_) * KD + colh] =
                    packh2(v[2] * scale, v[3] * scale);
            } else {
                atomicAdd(&pC[(size_t)r0 * KD + cc],     v[0]);
                atomicAdd(&pC[(size_t)r0 * KD + cc + 1], v[1]);
                atomicAdd(&pC[(size_t)r1 * KD + cc],     v[2]);
                atomicAdd(&pC[(size_t)r1 * KD + cc + 1], v[3]);
            }
        }
    }
}

#define SM_GEMM (2 * (128 * LDSW + 128 * LDSW) * 2)   // 40960

// ===========================================================================
// Fused flash attention — transposed PV (O^T = V^T P^T), P via smem
// ===========================================================================
#define FK   64                        // keys per chunk
#define NCH  (T / FK)                  // 32 chunks
#define LQ   264
#define LK   264
#define LV   72
#define LP   72
#define SMQ_BYTES (128 * LQ * 2)       // 67584 (reused for O staging)
#define SMK_BYTES (FK * LK * 2)        // 33792
#define SMV_BYTES (256 * LV * 2)       // 36864
#define OFF_P   (SMQ_BYTES + 2 * SMK_BYTES + 2 * SMV_BYTES)   // 208896
#define OFF_AL  (OFF_P + 128 * LP * 2)                        // 227328
#define SM_FLASH (OFF_AL + 128 * 4)                           // 227840

__global__ void __launch_bounds__(256, 1)
flash_kernel() {
    extern __shared__ __half sm[];
    char* smc = (char*)sm;
    const uint32_t sb = smem_u32(sm);
    const uint32_t sQ = sb;
    const uint32_t sK[2] = { sb + SMQ_BYTES, sb + SMQ_BYTES + SMK_BYTES };
    const uint32_t sV[2] = { sb + SMQ_BYTES + 2 * SMK_BYTES,
                             sb + SMQ_BYTES + 2 * SMK_BYTES + SMV_BYTES };
    const uint32_t sP = sb + OFF_P;
    __half* P_h      = (__half*)(smc + OFF_P);
    float*  alpha_s  = (float*)(smc + OFF_AL);

    const int tid = threadIdx.x;
    const int lane = tid & 31, wid = tid >> 5;
    const int g = lane >> 2, tig = lane & 3;
    const int lm_row = lane & 15, lm_k8 = (lane >> 4) * 8;

    const int q0 = blockIdx.x * 128;
    const int bh = blockIdx.y;
    const __half* __restrict__ Qg = g_Qh + ((size_t)bh * T + q0) * KD;
    const __half* __restrict__ Kg = g_Kh + (size_t)bh * T * KD;
    const __half* __restrict__ Vg = g_Vth + (size_t)bh * KD * T;

    {
        #pragma unroll
        for (int i = 0; i < 16; i++) {
            int idx = tid + i * 256;
            int r = idx >> 5, c = idx & 31;
            CP_ASYNC16(sQ + (uint32_t)((r * LQ + c * 8) * 2), Qg + r * KD + c * 8);
        }
    }
    auto issue_kv = [&](int ch, int buf) {
        const int s0 = ch * FK;
        #pragma unroll
        for (int i = 0; i < 8; i++) {
            int idx = tid + i * 256;
            int r = idx >> 5, c = idx & 31;
            CP_ASYNC16(sK[buf] + (uint32_t)((r * LK + c * 8) * 2),
                       Kg + (size_t)(s0 + r) * KD + c * 8);
        }
        #pragma unroll
        for (int i = 0; i < 8; i++) {
            int idx = tid + i * 256;
            int r = idx >> 3, c = idx & 7;
            CP_ASYNC16(sV[buf] + (uint32_t)((r * LV + c * 8) * 2),
                       Vg + (size_t)r * T + s0 + c * 8);
        }
    };

    issue_kv(0, 0);
    CP_COMMIT();
    issue_kv(1, 1);
    CP_COMMIT();

    // O^T accumulator: warp owns d in [wid*32, wid*32+32), all 128 q columns.
    float oaccT[2][16][4];
    #pragma unroll
    for (int mi = 0; mi < 2; mi++)
        #pragma unroll
        for (int nt = 0; nt < 16; nt++)
            #pragma unroll
            for (int r = 0; r < 4; r++) oaccT[mi][nt][r] = 0.f;
    float m0 = -INFINITY, m1 = -INFINITY;     // per-warp rows wid*16+g, +8
    float l0 = 0.f, l1 = 0.f;

    const uint32_t qrow_base = sQ + (uint32_t)(((wid * 16 + lm_row) * LQ + lm_k8) * 2);

    for (int ch = 0; ch < NCH; ch++) {
        if (ch < NCH - 1) CP_WAIT(1); else CP_WAIT(0);
        __syncthreads();
        const int buf = ch & 1;
        const uint32_t kfbase = sK[buf] + (uint32_t)((lm_row * LK + lm_k8) * 2);

        // ---- S = Q K^T (rows wid*16..+16, keys 0..64), double-buffered ----
        float sacc[8][4];
        #pragma unroll
        for (int n = 0; n < 8; n++)
            #pragma unroll
            for (int r = 0; r < 4; r++) sacc[n][r] = 0.f;

        uint32_t af2[2][4], bf2[2][8][2];
        LDSM_X4(af2[0][0], af2[0][1], af2[0][2], af2[0][3], qrow_base);
        #pragma unroll
        for (int nj = 0; nj < 4; nj++) {
            LDSM_X4(bf2[0][2 * nj][0], bf2[0][2 * nj + 1][0],
                    bf2[0][2 * nj][1], bf2[0][2 * nj + 1][1],
                    kfbase + (uint32_t)(nj * 16 * LK * 2));
        }
        #pragma unroll
        for (int ks = 0; ks < 16; ks++) {
            const int cur = ks & 1, nxt = cur ^ 1;
            if (ks < 15) {
                const uint32_t ko = (uint32_t)((ks + 1) * 32);
                LDSM_X4(af2[nxt][0], af2[nxt][1], af2[nxt][2], af2[nxt][3],
                        qrow_base + ko);
                #pragma unroll
                for (int nj = 0; nj < 4; nj++) {
                    LDSM_X4(bf2[nxt][2 * nj][0], bf2[nxt][2 * nj + 1][0],
                            bf2[nxt][2 * nj][1], bf2[nxt][2 * nj + 1][1],
                            kfbase + (uint32_t)(nj * 16 * LK * 2) + ko);
                }
            }
            #pragma unroll
            for (int nt = 0; nt < 8; nt++) mma16(sacc[nt], af2[cur], bf2[cur][nt]);
        }

        // ---- row max + alpha ----
        float cm0 = -INFINITY, cm1 = -INFINITY;
        #pragma unroll
        for (int nt = 0; nt < 8; nt++) {
            cm0 = fmaxf(cm0, fmaxf(sacc[nt][0], sacc[nt][1]));
            cm1 = fmaxf(cm1, fmaxf(sacc[nt][2], sacc[nt][3]));
        }
        cm0 = fmaxf(cm0, __shfl_xor_sync(0xffffffffu, cm0, 1));
        cm0 = fmaxf(cm0, __shfl_xor_sync(0xffffffffu, cm0, 2));
        cm1 = fmaxf(cm1, __shfl_xor_sync(0xffffffffu, cm1, 1));
        cm1 = fmaxf(cm1, __shfl_xor_sync(0xffffffffu, cm1, 2));

        const float mn0 = fmaxf(m0, cm0), mn1 = fmaxf(m1, cm1);
        const float al0 = exp2f(m0 - mn0), al1 = exp2f(m1 - mn1);
        m0 = mn0; m1 = mn1;
        if (tig == 0) {
            alpha_s[wid * 16 + g]     = al0;
            alpha_s[wid * 16 + g + 8] = al1;
        }

        // ---- preload V A-frags (independent of P; hides under softmax) ----
        uint32_t av[4][2][4];
        #pragma unroll
        for (int kst = 0; kst < 4; kst++)
            #pragma unroll
            for (int mi = 0; mi < 2; mi++) {
                uint32_t ad = sV[buf] +
                    (uint32_t)(((wid * 32 + mi * 16 + lm_row) * LV +
                                kst * 16 + lm_k8) * 2);
                LDSM_X4(av[kst][mi][0], av[kst][mi][1],
                        av[kst][mi][2], av[kst][mi][3], ad);
            }

        // ---- exp + row-sum + store P to smem ----
        float rs0 = 0.f, rs1 = 0.f;
        const int pr0 = (wid * 16 + g) * LP + tig * 2;
        const int pr1 = pr0 + 8 * LP;
        #pragma unroll
        for (int nt = 0; nt < 8; nt++) {
            float s0 = exp2f(sacc[nt][0] - mn0);
            float s1 = exp2f(sacc[nt][1] - mn0);
            float s2 = exp2f(sacc[nt][2] - mn1);
            float s3 = exp2f(sacc[nt][3] - mn1);
            rs0 += s0 + s1;
            rs1 += s2 + s3;
            *(uint32_t*)&P_h[pr0 + nt * 8] = packh2(s0, s1);
            *(uint32_t*)&P_h[pr1 + nt * 8] = packh2(s2, s3);
        }
        rs0 += __shfl_xor_sync(0xffffffffu, rs0, 1);
        rs0 += __shfl_xor_sync(0xffffffffu, rs0, 2);
        rs1 += __shfl_xor_sync(0xffffffffu, rs1, 1);
        rs1 += __shfl_xor_sync(0xffffffffu, rs1, 2);
        l0 = l0 * al0 + rs0;
        l1 = l1 * al1 + rs1;

        __syncthreads();   // P + alpha visible; sK/sV[buf] fully consumed

        if (ch + 2 < NCH) { issue_kv(ch + 2, buf); CP_COMMIT(); }

        // ---- rescale O^T by alpha (per q column) ----
        #pragma unroll
        for (int nt = 0; nt < 16; nt++) {
            float2 a2 = *(float2*)&alpha_s[nt * 8 + tig * 2];
            #pragma unroll
            for (int mi = 0; mi < 2; mi++) {
                oaccT[mi][nt][0] *= a2.x; oaccT[mi][nt][1] *= a2.y;
                oaccT[mi][nt][2] *= a2.x; oaccT[mi][nt][3] *= a2.y;
            }
        }

        // ---- O^T += V^T P^T ----
        #pragma unroll
        for (int kst = 0; kst < 4; kst++) {
            uint32_t pb[16][2];
            #pragma unroll
            for (int nj = 0; nj < 8; nj++) {
                uint32_t bd = sP +
                    (uint32_t)(((nj * 16 + lm_row) * LP + kst * 16 + lm_k8) * 2);
                LDSM_X4(pb[2 * nj][0], pb[2 * nj + 1][0],
                        pb[2 * nj][1], pb[2 * nj + 1][1], bd);
            }
            #pragma unroll
            for (int mi = 0; mi < 2; mi++)
                #pragma unroll
                for (int nt = 0; nt < 16; nt++)
                    mma16(oaccT[mi][nt], av[kst][mi], pb[nt]);
        }
    }

    // ---- epilogue: broadcast 1/l, normalize, stage O[q][d], write ----
    __syncthreads();
    if (tig == 0) {
        alpha_s[wid * 16 + g]     = 1.0f / l0;
        alpha_s[wid * 16 + g + 8] = 1.0f / l1;
    }
    __syncthreads();

    #pragma unroll
    for (int nt = 0; nt < 16; nt++) {
        float2 iv = *(float2*)&alpha_s[nt * 8 + tig * 2];
        const int q = nt * 8 + tig * 2;
        #pragma unroll
        for (int mi = 0; mi < 2; mi++) {
            const int d = wid * 32 + mi * 16 + g;
            sm[(q)     * LQ + d]     = __float2half_rn(oaccT[mi][nt][0] * iv.x);
            sm[(q + 1) * LQ + d]     = __float2half_rn(oaccT[mi][nt][1] * iv.y);
            sm[(q)     * LQ + d + 8] = __float2half_rn(oaccT[mi][nt][2] * iv.x);
            sm[(q + 1) * LQ + d + 8] = __float2half_rn(oaccT[mi][nt][3] * iv.y);
        }
    }
    __syncthreads();

    {
        const int q = tid >> 1, off = (tid & 1) * 128;
        const int b_ = bh >> 3, head = bh & 7;
        __half* dst = g_Oh + ((size_t)(b_ * T + q0 + q)) * NPROJ + head * KD + off;
        const __half* src = sm + q * LQ + off;
        #pragma unroll
        for (int j = 0; j < 16; j++)          // FIX: 16 x uint4 = 128 halves
            ((uint4*)dst)[j] = ((const uint4*)src)[j];
    }
}

// ---------------------------------------------------------------------------
// Merged prep kernel: grid (512, 6); y = task
// ---------------------------------------------------------------------------
__global__ void prep_kernel(const float* __restrict__ x,
                            const float* __restrict__ Wq,
                            const float* __restrict__ Wk,
                            const float* __restrict__ Wv,
                            const float* __restrict__ Wu,
                            const float* __restrict__ bu,
                            float* __restrict__ out) {
    const int task = blockIdx.y;
    const int tid = threadIdx.x;
    if (task == 0) {
        const int base = (blockIdx.x * 256 + tid) * 8;
        float4 a = *(const float4*)&x[base];
        float4 b = *(const float4*)&x[base + 4];
        *(uint2*)&g_Xh[base]     = make_uint2(packh2(a.x, a.y), packh2(a.z, a.w));
        *(uint2*)&g_Xh[base + 4] = make_uint2(packh2(b.x, b.y), packh2(b.z, b.w));
        return;
    }
    if (task == 5) {
        const int base = (blockIdx.x * 256 + tid) * 8;
        const int c0 = base & 255;
        float4 b0 = *(const float4*)&bu[c0];
        float4 b1 = *(const float4*)&bu[c0 + 4];
        *(float4*)&out[base]     = b0;
        *(float4*)&out[base + 4] = b1;
        return;
    }
    __shared__ float t[32][33];
    const int xx = tid & 31, yy = tid >> 5;
    if (task <= 3) {
        const float* in = (task == 1) ? Wq : (task == 2) ? Wk : Wv;
        __half* outw = g_Wth + (size_t)(task - 1) * NPROJ * KD;
        const int bx = blockIdx.x & 63, by = blockIdx.x >> 6;   // grid (64, 8)
        const int c0 = bx * 32, r0 = by * 32;
        #pragma unroll
        for (int i = 0; i < 32; i += 8)
            t[yy + i][xx] = in[(size_t)(r0 + yy + i) * NPROJ + c0 + xx];
        __syncthreads();
        #pragma unroll
        for (int i = 0; i < 32; i += 8)
            outw[(size_t)(c0 + yy + i) * KD + r0 + xx] = __float2half_rn(t[xx][yy + i]);
    } else {
        const int bx = blockIdx.x & 7, by = blockIdx.x >> 3;    // grid (8, 64)
        const int c0 = bx * 32, r0 = by * 32;
        #pragma unroll
        for (int i = 0; i < 32; i += 8)
            t[yy + i][xx] = Wu[(size_t)(r0 + yy + i) * KD + c0 + xx];
        __syncthreads();
        #pragma unroll
        for (int i = 0; i < 32; i += 8)
            g_Wuth[(size_t)(c0 + yy + i) * NPROJ + r0 + xx] = __float2half_rn(t[xx][yy + i]);
    }
}

// ---------------------------------------------------------------------------
extern "C" void kernel_launch(void* const* d_in, const int* in_sizes, int n_in,
                              void* d_out, int out_size) {
    const float* x  = (const float*)d_in[0];
    const float* Wq = (const float*)d_in[1];
    const float* Wk = (const float*)d_in[2];
    const float* Wv = (const float*)d_in[3];
    const float* Wu = (const float*)d_in[4];
    const float* bu = (const float*)d_in[5];
    float* out = (float*)d_out;

    cudaFuncSetAttribute(flash_kernel,
                         cudaFuncAttributeMaxDynamicSharedMemorySize, SM_FLASH);

    // 0) one-shot prep (x->fp16, weight transposes, out := bias)
    prep_kernel<<<dim3(512, 6), 256>>>(x, Wq, Wk, Wv, Wu, bu, out);

    // 1) projections (z = {q,k,v}); V transposed via smem; Q has log2e folded
    gemm_mma<MODE_PROJ><<<dim3(NPROJ / 128, ROWS / 128, 3), 256, SM_GEMM>>>(
        nullptr, nullptr);

    // 2) fused attention -> g_Oh
    flash_kernel<<<dim3(T / 128, BH), 256, SM_FLASH>>>();

    // 3) out += O @ Wu (split-K=4, atomic accumulate onto bias), 128x128 tiles
    gemm_mma<MODE_FINAL><<<dim3(KD / 128, ROWS / 128, KSPLIT), 256, SM_GEMM>>>(
        nullptr, out);
}

// round 14
// speedup vs baseline: 1.0547x; 1.0547x over previous
#include <cuda_runtime.h>
#include <cuda_fp16.h>
#include <math.h>
#include <stdint.h>

// Problem shape (fixed)
#define B   2
#define T   2048
#define KD  256
#define H   8
#define BH  (B*H)        // 16
#define NPROJ (KD*H)     // 2048
#define ROWS (B*T)       // 4096

#define LOG2E 1.4426950408889634f
#define KSPLIT 8

// ---------------------------------------------------------------------------
// Scratch (device globals — allocation-free per harness rules)
// ---------------------------------------------------------------------------
__device__ __half g_Xh [ROWS * KD];            // x in fp16
__device__ __half g_Qh [BH * T * KD];          // [bh][t][kd] * 0.25*log2e
__device__ __half g_Kh [BH * T * KD];          // [bh][t][kd] * 0.25
__device__ __half g_Vth[BH * KD * T];          // [bh][kd][t]
__device__ __half g_Oh [ROWS * NPROJ];         // [b*t][h*kd]
__device__ __half g_Wth [3 * NPROJ * KD];      // Wq^T,Wk^T,Wv^T fp16 [n][k]
__device__ __half g_Wuth[KD * NPROJ];          // Wu^T fp16 [256][2048]

// ---------------------------------------------------------------------------
// Common PTX helpers
// ---------------------------------------------------------------------------
__device__ __forceinline__ uint32_t smem_u32(const void* p) {
    uint32_t a;
    asm("{ .reg .u64 t; cvta.to.shared.u64 t, %1; cvt.u32.u64 %0, t; }"
        : "=r"(a) : "l"(p));
    return a;
}
__device__ __forceinline__ uint32_t packh2(float x, float y) {
    __half2 h = __floats2half2_rn(x, y);
    return *(uint32_t*)&h;
}
#define LDSM_X4(r0, r1, r2, r3, addr) \
    asm volatile("ldmatrix.sync.aligned.m8n8.x4.shared.b16 {%0,%1,%2,%3}, [%4];" \
                 : "=r"(r0), "=r"(r1), "=r"(r2), "=r"(r3) : "r"(addr))
#define CP_ASYNC16(dst, src) \
    asm volatile("cp.async.cg.shared.global [%0], [%1], 16;" :: "r"(dst), "l"(src))
#define CP_COMMIT() asm volatile("cp.async.commit_group;" ::: "memory")
#define CP_WAIT(n)  asm volatile("cp.async.wait_group %0;" :: "n"(n) : "memory")

__device__ __forceinline__ void mma16(float c[4], const uint32_t a[4],
                                      const uint32_t b[2]) {
    asm volatile(
        "mma.sync.aligned.m16n8k16.row.col.f32.f16.f16.f32 "
        "{%0,%1,%2,%3}, {%4,%5,%6,%7}, {%8,%9}, {%0,%1,%2,%3};"
        : "+f"(c[0]), "+f"(c[1]), "+f"(c[2]), "+f"(c[3])
        : "r"(a[0]), "r"(a[1]), "r"(a[2]), "r"(a[3]), "r"(b[0]), "r"(b[1]));
}

// ===========================================================================
// GEMM engine (proj: 128x128 tiles; final: 64x128 tiles, split-K=8)
// ===========================================================================
#define BK    32
#define LDSW  40

#define MODE_PROJ   0
#define MODE_FINAL  3

template <int MODE>
__global__ void __launch_bounds__(256, 2)
gemm_mma(const float* __restrict__ pBias, float* __restrict__ pC) {
    constexpr int TM = (MODE == MODE_PROJ) ? 128 : 64;
    constexpr int TN = 128;
    constexpr int MI = TM / 32;            // m-tiles per warp
    constexpr int ABUF = TM * LDSW;        // halves
    constexpr int BBUF = TN * LDSW;

    extern __shared__ __half smem[];
    const uint32_t sb0 = smem_u32(smem);
    const uint32_t aB[2] = { sb0, sb0 + ABUF * 2 };
    const uint32_t bB[2] = { sb0 + 2 * ABUF * 2, sb0 + 2 * ABUF * 2 + BBUF * 2 };

    const int tid  = threadIdx.x;
    const int lane = tid & 31, wid = tid >> 5;
    const int g    = lane >> 2, tig = lane & 3;
    const int wm   = (wid & 1) * (TM / 2);
    const int wn   = (wid >> 1) * 32;
    const int m0   = blockIdx.y * TM, n0 = blockIdx.x * TN;
    const int z    = blockIdx.z;

    const __half *Ah, *Bh;
    int lda, ldb, nch, kbase;
    if (MODE == MODE_PROJ) {
        Ah = g_Xh; lda = KD;
        Bh = g_Wth + (size_t)z * NPROJ * KD; ldb = KD;
        nch = KD / BK; kbase = 0;
    } else {
        Ah = g_Oh;   lda = NPROJ;
        Bh = g_Wuth; ldb = NPROJ;
        nch = NPROJ / BK / KSPLIT;               // 8 chunks per split
        kbase = z * (NPROJ / KSPLIT);            // 256 * z
    }

    auto issue_chunk = [&](int c, int st) {
        const int k0 = kbase + c * BK;
        #pragma unroll
        for (int u = tid; u < TM * 4; u += 256) {
            const int r = u >> 2, cc = (u & 3) * 8;
            CP_ASYNC16(aB[st] + (uint32_t)((r * LDSW + cc) * 2),
                       &Ah[(size_t)(m0 + r) * lda + k0 + cc]);
        }
        #pragma unroll
        for (int u = tid; u < TN * 4; u += 256) {
            const int r = u >> 2, cc = (u & 3) * 8;
            CP_ASYNC16(bB[st] + (uint32_t)((r * LDSW + cc) * 2),
                       &Bh[(size_t)(n0 + r) * ldb + k0 + cc]);
        }
    };

    float acc[MI][4][4];
    #pragma unroll
    for (int mi = 0; mi < MI; mi++)
        #pragma unroll
        for (int ni = 0; ni < 4; ni++)
            #pragma unroll
            for (int r = 0; r < 4; r++) acc[mi][ni][r] = 0.f;

    const int lm_row = lane & 15, lm_k8 = (lane >> 4) * 8;

    issue_chunk(0, 0); CP_COMMIT();
    issue_chunk(1, 1); CP_COMMIT();

    for (int c = 0; c < nch; c++) {
        const int st = c & 1;
        if (c + 1 < nch) CP_WAIT(1); else CP_WAIT(0);
        __syncthreads();
        #pragma unroll
        for (int ks = 0; ks < 2; ks++) {
            const int k = ks * 16;
            uint32_t af[MI][4], bf[4][2];
            #pragma unroll
            for (int mi = 0; mi < MI; mi++) {
                uint32_t ad = aB[st] +
                    (uint32_t)(((wm + mi * 16 + lm_row) * LDSW + k + lm_k8) * 2);
                LDSM_X4(af[mi][0], af[mi][1], af[mi][2], af[mi][3], ad);
            }
            #pragma unroll
            for (int nj = 0; nj < 2; nj++) {
                uint32_t bd = bB[st] +
                    (uint32_t)(((wn + nj * 16 + lm_row) * LDSW + k + lm_k8) * 2);
                LDSM_X4(bf[2 * nj][0], bf[2 * nj + 1][0],
                        bf[2 * nj][1], bf[2 * nj + 1][1], bd);
            }
            #pragma unroll
            for (int mi = 0; mi < MI; mi++)
                #pragma unroll
                for (int ni = 0; ni < 4; ni++)
                    mma16(acc[mi][ni], af[mi], bf[ni]);
        }
        __syncthreads();
        if (c + 2 < nch) { issue_chunk(c + 2, st); CP_COMMIT(); }
    }

    // ------------------- epilogue -------------------------------
    if (MODE == MODE_PROJ && z == 2) {
        // V: stage transposed tile in smem, then coalesced column writes.
        __half* epi = smem;
        #pragma unroll
        for (int mi = 0; mi < MI; mi++) {
            const int rl0 = wm + mi * 16 + g;
            #pragma unroll
            for (int ni = 0; ni < 4; ni++) {
                const int cl = wn + ni * 8 + tig * 2;
                const float* v = acc[mi][ni];
                epi[(cl)     * 136 + rl0]     = __float2half_rn(v[0]);
                epi[(cl + 1) * 136 + rl0]     = __float2half_rn(v[1]);
                epi[(cl)     * 136 + rl0 + 8] = __float2half_rn(v[2]);
                epi[(cl + 1) * 136 + rl0 + 8] = __float2half_rn(v[3]);
            }
        }
        __syncthreads();
        const int head = n0 >> 8;
        const int colh0 = n0 & 255;
        const int b_ = m0 >> 11, t0 = m0 & 2047;
        const int col = tid >> 1, sub = tid & 1;
        __half* dst = g_Vth + (((size_t)(b_ * H + head)) * KD + colh0 + col) * T + t0;
        #pragma unroll
        for (int j = 0; j < 8; j++) {
            const int row = sub * 8 + j * 16;
            *(uint4*)&dst[row] = *(const uint4*)&epi[col * 136 + row];
        }
        return;
    }

    #pragma unroll
    for (int mi = 0; mi < MI; mi++) {
        const int r0 = m0 + wm + mi * 16 + g;
        const int r1 = r0 + 8;
        #pragma unroll
        for (int ni = 0; ni < 4; ni++) {
            const int cc = n0 + wn + ni * 8 + tig * 2;
            const float* v = acc[mi][ni];
            if (MODE == MODE_PROJ) {
                const int head = n0 >> 8;
                const int colh = (n0 & 255) + wn + ni * 8 + tig * 2;
                const int b0_ = r0 >> 11, t0_ = r0 & 2047;
                const int b1_ = r1 >> 11, t1_ = r1 & 2047;
                const float scale = (z == 0) ? 0.25f * LOG2E : 0.25f;
                __half* Cb = (z == 0) ? g_Qh : g_Kh;
                *(uint32_t*)&Cb[(((size_t)(b0_ * H + head)) * T + t0_) * KD + colh] =
                    packh2(v[0] * scale, v[1] * scale);
                *(uint32_t*)&Cb[(((size_t)(b1_ * H + head)) * T + t1_) * KD + colh] =
                    packh2(v[2] * scale, v[3] * scale);
            } else {
                // split-K: accumulate into bias-initialized output
                atomicAdd(&pC[(size_t)r0 * KD + cc],     v[0]);
                atomicAdd(&pC[(size_t)r0 * KD + cc + 1], v[1]);
                atomicAdd(&pC[(size_t)r1 * KD + cc],     v[2]);
                atomicAdd(&pC[(size_t)r1 * KD + cc + 1], v[3]);
            }
        }
    }
}

#define SM_GEMM_PROJ  (2 * (128 * LDSW + 128 * LDSW) * 2)   // 40960
#define SM_GEMM_FINAL (2 * (64 * LDSW + 128 * LDSW) * 2)    // 30720

// ===========================================================================
// Fused flash attention — R11 version (S-phase fragment double-buffering,
// exp2 softmax interleaved with PV MMA)
// ===========================================================================
#define FK   64                        // keys per chunk
#define NCH  (T / FK)                  // 32 chunks
#define LQ   264
#define LK   264
#define LV   72
#define SMQ_BYTES (128 * LQ * 2)
#define SMK_BYTES (FK * LK * 2)
#define SMV_BYTES (256 * LV * 2)
#define SM_FLASH (SMQ_BYTES + 2 * SMK_BYTES + 2 * SMV_BYTES)   // 208896

__global__ void __launch_bounds__(256, 1)
flash_kernel() {
    extern __shared__ __half sm[];
    const uint32_t sb = smem_u32(sm);
    const uint32_t sQ = sb;
    const uint32_t sK[2] = { sb + SMQ_BYTES, sb + SMQ_BYTES + SMK_BYTES };
    const uint32_t sV[2] = { sb + SMQ_BYTES + 2 * SMK_BYTES,
                             sb + SMQ_BYTES + 2 * SMK_BYTES + SMV_BYTES };

    const int tid = threadIdx.x;
    const int lane = tid & 31, wid = tid >> 5;
    const int g = lane >> 2, tig = lane & 3;
    const int lm_row = lane & 15, lm_k8 = (lane >> 4) * 8;

    const int q0 = blockIdx.x * 128;
    const int bh = blockIdx.y;
    const __half* __restrict__ Qg = g_Qh + ((size_t)bh * T + q0) * KD;
    const __half* __restrict__ Kg = g_Kh + (size_t)bh * T * KD;
    const __half* __restrict__ Vg = g_Vth + (size_t)bh * KD * T;

    {
        #pragma unroll
        for (int i = 0; i < 16; i++) {
            int idx = tid + i * 256;
            int r = idx >> 5, c = idx & 31;
            CP_ASYNC16(sQ + (uint32_t)((r * LQ + c * 8) * 2), Qg + r * KD + c * 8);
        }
    }
    auto issue_kv = [&](int ch, int buf) {
        const int s0 = ch * FK;
        #pragma unroll
        for (int i = 0; i < 8; i++) {
            int idx = tid + i * 256;
            int r = idx >> 5, c = idx & 31;
            CP_ASYNC16(sK[buf] + (uint32_t)((r * LK + c * 8) * 2),
                       Kg + (size_t)(s0 + r) * KD + c * 8);
        }
        #pragma unroll
        for (int i = 0; i < 8; i++) {
            int idx = tid + i * 256;
            int r = idx >> 3, c = idx & 7;
            CP_ASYNC16(sV[buf] + (uint32_t)((r * LV + c * 8) * 2),
                       Vg + (size_t)r * T + s0 + c * 8);
        }
    };

    issue_kv(0, 0);
    CP_COMMIT();
    issue_kv(1, 1);
    CP_COMMIT();

    float oacc[32][4];
    #pragma unroll
    for (int n = 0; n < 32; n++)
        #pragma unroll
        for (int r = 0; r < 4; r++) oacc[n][r] = 0.f;
    float m0 = -INFINITY, m1 = -INFINITY;
    float l0 = 0.f, l1 = 0.f;

    const uint32_t qrow_base = sQ + (uint32_t)(((wid * 16 + lm_row) * LQ + lm_k8) * 2);

    for (int ch = 0; ch < NCH; ch++) {
        if (ch < NCH - 1) CP_WAIT(1); else CP_WAIT(0);
        __syncthreads();
        const int buf = ch & 1;
        const uint32_t kbase = sK[buf] + (uint32_t)((lm_row * LK + lm_k8) * 2);

        // ---- S = Q K^T, fragment double-buffered over ks ----
        float sacc[8][4];
        #pragma unroll
        for (int n = 0; n < 8; n++)
            #pragma unroll
            for (int r = 0; r < 4; r++) sacc[n][r] = 0.f;

        uint32_t af2[2][4], bf2[2][8][2];
        LDSM_X4(af2[0][0], af2[0][1], af2[0][2], af2[0][3], qrow_base);
        #pragma unroll
        for (int nj = 0; nj < 4; nj++) {
            LDSM_X4(bf2[0][2 * nj][0], bf2[0][2 * nj + 1][0],
                    bf2[0][2 * nj][1], bf2[0][2 * nj + 1][1],
                    kbase + (uint32_t)(nj * 16 * LK * 2));
        }
        #pragma unroll
        for (int ks = 0; ks < 16; ks++) {
            const int cur = ks & 1, nxt = cur ^ 1;
            if (ks < 15) {
                const uint32_t ko = (uint32_t)((ks + 1) * 32);
                LDSM_X4(af2[nxt][0], af2[nxt][1], af2[nxt][2], af2[nxt][3],
                        qrow_base + ko);
                #pragma unroll
                for (int nj = 0; nj < 4; nj++) {
                    LDSM_X4(bf2[nxt][2 * nj][0], bf2[nxt][2 * nj + 1][0],
                            bf2[nxt][2 * nj][1], bf2[nxt][2 * nj + 1][1],
                            kbase + (uint32_t)(nj * 16 * LK * 2) + ko);
                }
            }
            #pragma unroll
            for (int nt = 0; nt < 8; nt++) mma16(sacc[nt], af2[cur], bf2[cur][nt]);
        }

        // ---- max reduction + rescale ----
        float cm0 = -INFINITY, cm1 = -INFINITY;
        #pragma unroll
        for (int nt = 0; nt < 8; nt++) {
            cm0 = fmaxf(cm0, fmaxf(sacc[nt][0], sacc[nt][1]));
            cm1 = fmaxf(cm1, fmaxf(sacc[nt][2], sacc[nt][3]));
        }
        cm0 = fmaxf(cm0, __shfl_xor_sync(0xffffffffu, cm0, 1));
        cm0 = fmaxf(cm0, __shfl_xor_sync(0xffffffffu, cm0, 2));
        cm1 = fmaxf(cm1, __shfl_xor_sync(0xffffffffu, cm1, 1));
        cm1 = fmaxf(cm1, __shfl_xor_sync(0xffffffffu, cm1, 2));

        const float mn0 = fmaxf(m0, cm0), mn1 = fmaxf(m1, cm1);
        const float al0 = exp2f(m0 - mn0), al1 = exp2f(m1 - mn1);
        m0 = mn0; m1 = mn1;

        #pragma unroll
        for (int n = 0; n < 32; n++) {
            oacc[n][0] *= al0; oacc[n][1] *= al0;
            oacc[n][2] *= al1; oacc[n][3] *= al1;
        }

        // ---- interleaved: exp/pack k-step ks2, then its PV MMAs ----
        float rs0 = 0.f, rs1 = 0.f;
        #pragma unroll
        for (int ks2 = 0; ks2 < 4; ks2++) {
            const int e0 = 2 * ks2, e1 = 2 * ks2 + 1;
            sacc[e0][0] = exp2f(sacc[e0][0] - mn0);
            sacc[e0][1] = exp2f(sacc[e0][1] - mn0);
            sacc[e0][2] = exp2f(sacc[e0][2] - mn1);
            sacc[e0][3] = exp2f(sacc[e0][3] - mn1);
            sacc[e1][0] = exp2f(sacc[e1][0] - mn0);
            sacc[e1][1] = exp2f(sacc[e1][1] - mn0);
            sacc[e1][2] = exp2f(sacc[e1][2] - mn1);
            sacc[e1][3] = exp2f(sacc[e1][3] - mn1);
            rs0 += sacc[e0][0] + sacc[e0][1] + sacc[e1][0] + sacc[e1][1];
            rs1 += sacc[e0][2] + sacc[e0][3] + sacc[e1][2] + sacc[e1][3];

            uint32_t pa[4];
            pa[0] = packh2(sacc[e0][0], sacc[e0][1]);
            pa[1] = packh2(sacc[e0][2], sacc[e0][3]);
            pa[2] = packh2(sacc[e1][0], sacc[e1][1]);
            pa[3] = packh2(sacc[e1][2], sacc[e1][3]);

            #pragma unroll
            for (int hv = 0; hv < 2; hv++) {
                uint32_t bv[16][2];
                #pragma unroll
                for (int nj = 0; nj < 8; nj++) {
                    uint32_t bd = sV[buf] +
                        (uint32_t)((((hv * 8 + nj) * 16 + lm_row) * LV +
                                    ks2 * 16 + lm_k8) * 2);
                    LDSM_X4(bv[2 * nj][0], bv[2 * nj + 1][0],
                            bv[2 * nj][1], bv[2 * nj + 1][1], bd);
                }
                #pragma unroll
                for (int nt = 0; nt < 16; nt++)
                    mma16(oacc[hv * 16 + nt], pa, bv[nt]);
            }
        }

        rs0 += __shfl_xor_sync(0xffffffffu, rs0, 1);
        rs0 += __shfl_xor_sync(0xffffffffu, rs0, 2);
        rs1 += __shfl_xor_sync(0xffffffffu, rs1, 1);
        rs1 += __shfl_xor_sync(0xffffffffu, rs1, 2);
        l0 = l0 * al0 + rs0;
        l1 = l1 * al1 + rs1;

        __syncthreads();
        if (ch + 2 < NCH) { issue_kv(ch + 2, buf); CP_COMMIT(); }
    }

    const float inv0 = 1.0f / l0, inv1 = 1.0f / l1;
    const int r0 = q0 + wid * 16 + g, r1 = r0 + 8;
    const int b_ = bh >> 3, head = bh & 7;
    __half* o0 = g_Oh + ((size_t)(b_ * T + r0)) * NPROJ + head * KD;
    __half* o1 = g_Oh + ((size_t)(b_ * T + r1)) * NPROJ + head * KD;
    #pragma unroll
    for (int nt = 0; nt < 32; nt++) {
        const int col = nt * 8 + tig * 2;
        *(uint32_t*)&o0[col] = packh2(oacc[nt][0] * inv0, oacc[nt][1] * inv0);
        *(uint32_t*)&o1[col] = packh2(oacc[nt][2] * inv1, oacc[nt][3] * inv1);
    }
}

// ---------------------------------------------------------------------------
// Merged prep kernel: grid (512, 6); y = task
//   0: convert x -> fp16; 1-3: transpose Wq/Wk/Wv; 4: transpose Wu
//   5: init out with bias (for split-K accumulation)
// ---------------------------------------------------------------------------
__global__ void prep_kernel(const float* __restrict__ x,
                            const float* __restrict__ Wq,
                            const float* __restrict__ Wk,
                            const float* __restrict__ Wv,
                            const float* __restrict__ Wu,
                            const float* __restrict__ bu,
                            float* __restrict__ out) {
    const int task = blockIdx.y;
    const int tid = threadIdx.x;
    if (task == 0) {
        const int base = (blockIdx.x * 256 + tid) * 8;
        float4 a = *(const float4*)&x[base];
        float4 b = *(const float4*)&x[base + 4];
        *(uint2*)&g_Xh[base]     = make_uint2(packh2(a.x, a.y), packh2(a.z, a.w));
        *(uint2*)&g_Xh[base + 4] = make_uint2(packh2(b.x, b.y), packh2(b.z, b.w));
        return;
    }
    if (task == 5) {
        const int base = (blockIdx.x * 256 + tid) * 8;
        const int c0 = base & 255;
        float4 b0 = *(const float4*)&bu[c0];
        float4 b1 = *(const float4*)&bu[c0 + 4];
        *(float4*)&out[base]     = b0;
        *(float4*)&out[base + 4] = b1;
        return;
    }
    __shared__ float t[32][33];
    const int xx = tid & 31, yy = tid >> 5;
    if (task <= 3) {
        const float* in = (task == 1) ? Wq : (task == 2) ? Wk : Wv;
        __half* outw = g_Wth + (size_t)(task - 1) * NPROJ * KD;
        const int bx = blockIdx.x & 63, by = blockIdx.x >> 6;   // grid (64, 8)
        const int c0 = bx * 32, r0 = by * 32;
        #pragma unroll
        for (int i = 0; i < 32; i += 8)
            t[yy + i][xx] = in[(size_t)(r0 + yy + i) * NPROJ + c0 + xx];
        __syncthreads();
        #pragma unroll
        for (int i = 0; i < 32; i += 8)
            outw[(size_t)(c0 + yy + i) * KD + r0 + xx] = __float2half_rn(t[xx][yy + i]);
    } else {
        const int bx = blockIdx.x & 7, by = blockIdx.x >> 3;    // grid (8, 64)
        const int c0 = bx * 32, r0 = by * 32;
        #pragma unroll
        for (int i = 0; i < 32; i += 8)
            t[yy + i][xx] = Wu[(size_t)(r0 + yy + i) * KD + c0 + xx];
        __syncthreads();
        #pragma unroll
        for (int i = 0; i < 32; i += 8)
            g_Wuth[(size_t)(c0 + yy + i) * NPROJ + r0 + xx] = __float2half_rn(t[xx][yy + i]);
    }
}

// ---------------------------------------------------------------------------
extern "C" void kernel_launch(void* const* d_in, const int* in_sizes, int n_in,
                              void* d_out, int out_size) {
    const float* x  = (const float*)d_in[0];
    const float* Wq = (const float*)d_in[1];
    const float* Wk = (const float*)d_in[2];
    const float* Wv = (const float*)d_in[3];
    const float* Wu = (const float*)d_in[4];
    const float* bu = (const float*)d_in[5];
    float* out = (float*)d_out;

    cudaFuncSetAttribute(flash_kernel,
                         cudaFuncAttributeMaxDynamicSharedMemorySize, SM_FLASH);

    // 0) one-shot prep (x->fp16, weight transposes, out := bias)
    prep_kernel<<<dim3(512, 6), 256>>>(x, Wq, Wk, Wv, Wu, bu, out);

    // 1) projections (z = {q,k,v}); V transposed via smem; Q has log2e folded
    gemm_mma<MODE_PROJ><<<dim3(NPROJ / 128, ROWS / 128, 3), 256, SM_GEMM_PROJ>>>(
        nullptr, nullptr);

    // 2) fused attention -> g_Oh
    flash_kernel<<<dim3(T / 128, BH), 256, SM_FLASH>>>();

    // 3) out += O @ Wu (split-K=8, atomic accumulate onto bias)
    gemm_mma<MODE_FINAL><<<dim3(KD / 128, ROWS / 64, KSPLIT), 256, SM_GEMM_FINAL>>>(
        nullptr, out);
}